// round 1
// baseline (speedup 1.0000x reference)
#include <cuda_runtime.h>

// Problem constants
#define BB 8
#define DD 128
#define NH 8
#define LL 1024
#define DKK 16
#define BH (BB*NH)   // 64

// Scratch (device globals; no allocation APIs)
__device__ float g_Q[BH*DKK*LL];   // [bh][k][l]
__device__ float g_K[BH*DKK*LL];
__device__ float g_V[BH*DKK*LL];
__device__ float g_H[BB*DD*LL];    // head, [b][h*16+v][l]

typedef unsigned long long u64;

__device__ __forceinline__ void fma2(u64 &d, u64 a, u64 b) {
    asm("fma.rn.f32x2 %0, %1, %2, %0;" : "+l"(d) : "l"(a), "l"(b));
}
__device__ __forceinline__ void add2(u64 &d, u64 a) {
    asm("add.rn.f32x2 %0, %1, %0;" : "+l"(d) : "l"(a));
}
__device__ __forceinline__ u64 pack2(float lo, float hi) {
    u64 r; asm("mov.b64 %0, {%1, %2};" : "=l"(r) : "f"(lo), "f"(hi)); return r;
}
__device__ __forceinline__ float2 unpack2(u64 v) {
    float2 r; asm("mov.b64 {%0, %1}, %2;" : "=f"(r.x), "=f"(r.y) : "l"(v)); return r;
}
__device__ __forceinline__ u64 dup2(float v) { return pack2(v, v); }

// ---------------------------------------------------------------------------
// Kernel A: QKV projection.  grid (64 bh, 16 l-chunks of 64), 192 threads.
// Q/K/V[bh][r][l] = sum_d W[h][b][r][d] * x[b][d][l]
// smem: wdup 48x128 u64 (48KB) + xs 128x64 f32 (32KB)
// ---------------------------------------------------------------------------
__global__ __launch_bounds__(192) void qkv_kernel(
    const float* __restrict__ x,
    const float* __restrict__ Wq,
    const float* __restrict__ Wk,
    const float* __restrict__ Wv)
{
    extern __shared__ char smem[];
    u64*   wdup = (u64*)smem;                       // [48][128]
    float* xs   = (float*)(smem + 48*128*8);        // [128][64]

    int bh = blockIdx.x;
    int b = bh >> 3, h = bh & 7;
    int l0 = blockIdx.y * 64;
    int tid = threadIdx.x;

    for (int e = tid; e < 48*128; e += 192) {
        int r = e >> 7, d = e & 127;
        float w;
        if (r < 16)      w = Wq[((h*8 + b)*16 + r     )*128 + d];
        else if (r < 32) w = Wk[((h*8 + b)*16 + (r-16))*128 + d];
        else             w = Wv[((h*8 + b)*16 + (r-32))*128 + d];
        wdup[e] = dup2(w);
    }
    for (int e = tid; e < 128*64; e += 192) {
        int d = e >> 6, c = e & 63;
        xs[e] = x[(b*128 + d)*1024 + l0 + c];
    }
    __syncthreads();

    int rowg = tid >> 4;      // 0..11
    int colg = tid & 15;      // 0..15
    int r0 = rowg*4, c0 = colg*4;

    u64 acc[4][2] = {};
    #pragma unroll 16
    for (int d = 0; d < 128; d++) {
        u64 xa = *(const u64*)(xs + d*64 + c0);
        u64 xb = *(const u64*)(xs + d*64 + c0 + 2);
        #pragma unroll
        for (int r = 0; r < 4; r++) {
            u64 w = wdup[(r0 + r)*128 + d];
            fma2(acc[r][0], w, xa);
            fma2(acc[r][1], w, xb);
        }
    }
    #pragma unroll
    for (int r = 0; r < 4; r++) {
        int gr = r0 + r;
        float2 a0 = unpack2(acc[r][0]), a1 = unpack2(acc[r][1]);
        float4 v4 = make_float4(a0.x, a0.y, a1.x, a1.y);
        float* dst;
        if (gr < 16)       dst = g_Q + (bh*16 + gr     )*1024;
        else if (gr < 32)  dst = g_K + (bh*16 + gr - 16)*1024;
        else               dst = g_V + (bh*16 + gr - 32)*1024;
        *(float4*)(dst + l0 + c0) = v4;
    }
}

// ---------------------------------------------------------------------------
// Kernel B: attention.  grid (64 bh, 2 j-tiles of 512), 128 threads.
// Each thread owns 4 output columns j (2 packed pairs).
// softmax over i of (Q_i . K_j * scale); head[v][j] = sum_i p_i V[v][i] / sum_i p_i
// Max subtraction unnecessary: |score| <~ 10, exp safe in fp32.
// ---------------------------------------------------------------------------
#define TJ 512
#define TI 64
__global__ __launch_bounds__(128) void attn_kernel()
{
    __shared__ u64 Qdup[16*TI];
    __shared__ u64 Vdup[16*TI];

    int bh  = blockIdx.x;
    int j0  = blockIdx.y * TJ;
    int tid = threadIdx.x;
    int c0  = j0 + tid*4;

    const float SCL = 0.25f * 1.4426950408889634f;  // scale * log2(e)

    u64 kp0[16], kp1[16];
    #pragma unroll
    for (int k = 0; k < 16; k++) {
        float4 kv = *(const float4*)(g_K + (bh*16 + k)*1024 + c0);
        kp0[k] = pack2(kv.x*SCL, kv.y*SCL);
        kp1[k] = pack2(kv.z*SCL, kv.w*SCL);
    }

    u64 acc0[16] = {}, acc1[16] = {};
    u64 lp0 = 0, lp1 = 0;

    for (int i0 = 0; i0 < 1024; i0 += TI) {
        __syncthreads();
        for (int e = tid; e < 16*TI; e += 128) {
            int k = e >> 6, ii = e & (TI-1);
            Qdup[e] = dup2(g_Q[(bh*16 + k)*1024 + i0 + ii]);
            Vdup[e] = dup2(g_V[(bh*16 + k)*1024 + i0 + ii]);
        }
        __syncthreads();

        for (int ii = 0; ii < TI; ii++) {
            u64 s0 = 0, s1 = 0;
            #pragma unroll
            for (int k = 0; k < 16; k++) {
                u64 q = Qdup[k*TI + ii];   // broadcast LDS.64
                fma2(s0, q, kp0[k]);
                fma2(s1, q, kp1[k]);
            }
            float2 sa = unpack2(s0), sb = unpack2(s1);
            u64 P0 = pack2(exp2f(sa.x), exp2f(sa.y));
            u64 P1 = pack2(exp2f(sb.x), exp2f(sb.y));
            add2(lp0, P0); add2(lp1, P1);
            #pragma unroll
            for (int v = 0; v < 16; v++) {
                u64 vv = Vdup[v*TI + ii];  // broadcast LDS.64
                fma2(acc0[v], P0, vv);
                fma2(acc1[v], P1, vv);
            }
        }
    }

    int b = bh >> 3, h = bh & 7;
    float2 la = unpack2(lp0), lb = unpack2(lp1);
    float r0 = 1.0f/la.x, r1 = 1.0f/la.y, r2 = 1.0f/lb.x, r3 = 1.0f/lb.y;
    #pragma unroll
    for (int v = 0; v < 16; v++) {
        float2 a = unpack2(acc0[v]), c = unpack2(acc1[v]);
        float4 o = make_float4(a.x*r0, a.y*r1, c.x*r2, c.y*r3);
        *(float4*)(g_H + (b*128 + h*16 + v)*1024 + c0) = o;
    }
}

// ---------------------------------------------------------------------------
// Kernel C: output projection. grid (8 b, 16 l-chunks of 64), 512 threads.
// out[b][o][l] = sum_d Wo[b][o][d] * head[b][d][l]
// smem: wdup 128x128 u64 (128KB) + hs 128x64 f32 (32KB)
// ---------------------------------------------------------------------------
__global__ __launch_bounds__(512) void outproj_kernel(
    const float* __restrict__ Wo, float* __restrict__ out)
{
    extern __shared__ char smem[];
    u64*   wdup = (u64*)smem;                    // [128][128]
    float* hs   = (float*)(smem + 128*128*8);    // [128][64]

    int b  = blockIdx.x;
    int l0 = blockIdx.y * 64;
    int tid = threadIdx.x;

    for (int e = tid; e < 128*128; e += 512)
        wdup[e] = dup2(Wo[b*128*128 + e]);
    for (int e = tid; e < 128*64; e += 512) {
        int d = e >> 6, c = e & 63;
        hs[e] = g_H[(b*128 + d)*1024 + l0 + c];
    }
    __syncthreads();

    int rowg = tid >> 4;    // 0..31
    int colg = tid & 15;    // 0..15
    int r0 = rowg*4, c0 = colg*4;

    u64 acc[4][2] = {};
    #pragma unroll 16
    for (int d = 0; d < 128; d++) {
        u64 xa = *(const u64*)(hs + d*64 + c0);
        u64 xb = *(const u64*)(hs + d*64 + c0 + 2);
        #pragma unroll
        for (int r = 0; r < 4; r++) {
            u64 w = wdup[(r0 + r)*128 + d];
            fma2(acc[r][0], w, xa);
            fma2(acc[r][1], w, xb);
        }
    }
    #pragma unroll
    for (int r = 0; r < 4; r++) {
        float2 a0 = unpack2(acc[r][0]), a1 = unpack2(acc[r][1]);
        *(float4*)(out + (b*128 + r0 + r)*1024 + l0 + c0) =
            make_float4(a0.x, a0.y, a1.x, a1.y);
    }
}

// ---------------------------------------------------------------------------
extern "C" void kernel_launch(void* const* d_in, const int* in_sizes, int n_in,
                              void* d_out, int out_size)
{
    const float* x  = (const float*)d_in[0];
    const float* Wq = (const float*)d_in[1];
    const float* Wk = (const float*)d_in[2];
    const float* Wv = (const float*)d_in[3];
    const float* Wo = (const float*)d_in[4];
    float* out = (float*)d_out;

    const int smemA = 48*128*8 + 128*64*4;    // 81920
    const int smemC = 128*128*8 + 128*64*4;   // 163840
    cudaFuncSetAttribute(qkv_kernel,     cudaFuncAttributeMaxDynamicSharedMemorySize, smemA);
    cudaFuncSetAttribute(outproj_kernel, cudaFuncAttributeMaxDynamicSharedMemorySize, smemC);

    qkv_kernel<<<dim3(BH, LL/64), 192, smemA>>>(x, Wq, Wk, Wv);
    attn_kernel<<<dim3(BH, LL/TJ), 128>>>();
    outproj_kernel<<<dim3(BB, LL/64), 512, smemC>>>(Wo, out);
}

// round 2
// speedup vs baseline: 1.2622x; 1.2622x over previous
#include <cuda_runtime.h>

#define BH 64
typedef unsigned long long u64;

// Scratch (device globals)
__device__ float g_Q[BH*16*1024];
__device__ float g_K[BH*16*1024];
__device__ float g_V[BH*16*1024];
__device__ float g_Hn[2*BH*16*1024];  // unnormalized numerators, [z][bh][v][l]
__device__ float g_Hs[2*BH*1024];     // colsums, [z][bh][l]

__device__ __forceinline__ void fma2(u64 &d, u64 a, u64 b) {
    asm("fma.rn.f32x2 %0, %1, %2, %0;" : "+l"(d) : "l"(a), "l"(b));
}
__device__ __forceinline__ void add2(u64 &d, u64 a) {
    asm("add.rn.f32x2 %0, %1, %0;" : "+l"(d) : "l"(a));
}
__device__ __forceinline__ u64 pack2(float lo, float hi) {
    u64 r; asm("mov.b64 %0, {%1, %2};" : "=l"(r) : "f"(lo), "f"(hi)); return r;
}
__device__ __forceinline__ float2 unpack2(u64 v) {
    float2 r; asm("mov.b64 {%0, %1}, %2;" : "=f"(r.x), "=f"(r.y) : "l"(v)); return r;
}
__device__ __forceinline__ u64 dup2(float v) { return pack2(v, v); }
__device__ __forceinline__ float ex2(float x) {
    float y; asm("ex2.approx.ftz.f32 %0, %1;" : "=f"(y) : "f"(x)); return y;
}

// ---------------------------------------------------------------------------
// Kernel A: QKV projection. grid (64 bh, 8 l-chunks of 128), 128 threads.
// Thread tile: 6 rows x 8 cols (4 col-pairs). smem 64KB -> 3 CTAs/SM.
// ---------------------------------------------------------------------------
__global__ __launch_bounds__(128) void qkv_kernel(
    const float* __restrict__ x,
    const float* __restrict__ Wq,
    const float* __restrict__ Wk,
    const float* __restrict__ Wv)
{
    extern __shared__ char sm[];
    u64*   wdup = (u64*)sm;                   // [48][128]
    float* xs   = (float*)(sm + 48*128*8);    // [32][128]

    int bh = blockIdx.x, b = bh >> 3, h = bh & 7;
    int l0 = blockIdx.y * 128;
    int tid = threadIdx.x;

    for (int e = tid; e < 48*128; e += 128) {
        int r = e >> 7, d = e & 127;
        const float* W = (r < 16) ? Wq : ((r < 32) ? Wk : Wv);
        wdup[e] = dup2(W[((h*8 + b)*16 + (r & 15))*128 + d]);
    }

    int rowg = tid >> 4, colg = tid & 15;
    int r0 = rowg*6, c0 = colg*8;

    u64 acc[6][4] = {};
    for (int ch = 0; ch < 4; ch++) {
        __syncthreads();
        for (int idx = tid; idx < 1024; idx += 128) {
            int dd = idx >> 5, c4 = (idx & 31) * 4;
            *(float4*)(xs + dd*128 + c4) =
                *(const float4*)(x + (b*128 + ch*32 + dd)*1024 + l0 + c4);
        }
        __syncthreads();
        #pragma unroll 8
        for (int dd = 0; dd < 32; dd++) {
            u64 xa[4];
            #pragma unroll
            for (int p = 0; p < 4; p++) xa[p] = *(const u64*)(xs + dd*128 + c0 + 2*p);
            #pragma unroll
            for (int r = 0; r < 6; r++) {
                u64 w = wdup[(r0 + r)*128 + ch*32 + dd];
                #pragma unroll
                for (int p = 0; p < 4; p++) fma2(acc[r][p], w, xa[p]);
            }
        }
    }
    #pragma unroll
    for (int r = 0; r < 6; r++) {
        int gr = r0 + r;
        float* dst = (gr < 16) ? g_Q : ((gr < 32) ? g_K : g_V);
        float2 a0 = unpack2(acc[r][0]), a1 = unpack2(acc[r][1]);
        float2 a2 = unpack2(acc[r][2]), a3 = unpack2(acc[r][3]);
        float* base = dst + (bh*16 + (gr & 15))*1024 + l0 + c0;
        *(float4*)(base)     = make_float4(a0.x, a0.y, a1.x, a1.y);
        *(float4*)(base + 4) = make_float4(a2.x, a2.y, a3.x, a3.y);
    }
}

// ---------------------------------------------------------------------------
// Kernel B: attention. grid (64 bh, 4 j-tiles of 256, 2 i-halves), 128 thr.
// Two-phase per 32-i block: P = exp(Q^T K) staged through smem, H += V*P.
// Writes unnormalized numerators + colsums; normalization fused in kernel C.
// ---------------------------------------------------------------------------
__global__ __launch_bounds__(128) void attn_kernel()
{
    extern __shared__ char sm[];
    u64* Kp = (u64*)sm;                       // [16][128]  16KB  (j-pairs, *SCL)
    u64* Ps = (u64*)(sm + 16384);             // [32][128]  32KB  (P j-pairs)
    u64* Qd = (u64*)(sm + 16384 + 32768);     // [16][32]   4KB   (dup)
    u64* Vd = Qd + 512;                       // [16][32]   4KB   (dup)

    int bh = blockIdx.x;
    int j0 = blockIdx.y * 256;
    int z  = blockIdx.z;
    int tid = threadIdx.x;
    const float SCL = 0.25f * 1.4426950408889634f;  // scale * log2(e)

    for (int e = tid; e < 2048; e += 128) {
        int k = e >> 7, s = e & 127;
        float2 kv = *(const float2*)(g_K + (bh*16 + k)*1024 + j0 + 2*s);
        Kp[e] = pack2(kv.x * SCL, kv.y * SCL);
    }

    int i_base = z * 512;
    float qf[4], vf[4];
    #pragma unroll
    for (int w = 0; w < 4; w++) {
        int e = tid + w*128, k = e >> 5, ii = e & 31;
        qf[w] = g_Q[(bh*16 + k)*1024 + i_base + ii];
        vf[w] = g_V[(bh*16 + k)*1024 + i_base + ii];
    }

    int ig = tid >> 4, jg = tid & 15;   // phase-1 tiling: 4 i's x 8 j-pair slots
    int vg = tid >> 6, pg = tid & 63;   // phase-2 tiling: 8 v's x 2 j-pairs

    u64 acc[8][2] = {};
    u64 sum0 = 0, sum1 = 0;

    for (int t = 0; t < 16; t++) {
        __syncthreads();                 // prev phase-2 done (Ps/Vd reusable)
        #pragma unroll
        for (int w = 0; w < 4; w++) {
            int e = tid + w*128;
            Qd[e] = dup2(qf[w]);
            Vd[e] = dup2(vf[w]);
        }
        int tn = (t + 1 < 16) ? t + 1 : 15;   // prefetch next block
        #pragma unroll
        for (int w = 0; w < 4; w++) {
            int e = tid + w*128, k = e >> 5, ii = e & 31;
            qf[w] = g_Q[(bh*16 + k)*1024 + i_base + tn*32 + ii];
            vf[w] = g_V[(bh*16 + k)*1024 + i_base + tn*32 + ii];
        }
        __syncthreads();                 // tiles ready

        // phase 1: S = Q^T K (scaled), then P = exp2(S) -> Ps
        u64 s[4][8] = {};
        #pragma unroll
        for (int k = 0; k < 16; k++) {
            u64 qr[4];
            #pragma unroll
            for (int r = 0; r < 4; r++) qr[r] = Qd[k*32 + ig*4 + r];
            #pragma unroll
            for (int p = 0; p < 8; p++) {
                u64 kv = Kp[k*128 + p*16 + jg];
                #pragma unroll
                for (int r = 0; r < 4; r++) fma2(s[r][p], qr[r], kv);
            }
        }
        #pragma unroll
        for (int r = 0; r < 4; r++) {
            #pragma unroll
            for (int p = 0; p < 8; p++) {
                float2 sv = unpack2(s[r][p]);
                Ps[(ig*4 + r)*128 + p*16 + jg] = pack2(ex2(sv.x), ex2(sv.y));
            }
        }
        __syncthreads();                 // Ps ready

        // phase 2: H += V * P; colsum += P
        #pragma unroll 4
        for (int ii = 0; ii < 32; ii++) {
            u64 P0 = Ps[ii*128 + 2*pg];
            u64 P1 = Ps[ii*128 + 2*pg + 1];
            add2(sum0, P0); add2(sum1, P1);
            #pragma unroll
            for (int r = 0; r < 8; r++) {
                u64 vv = Vd[(vg*8 + r)*32 + ii];
                fma2(acc[r][0], P0, vv);
                fma2(acc[r][1], P1, vv);
            }
        }
    }

    int zb = z*64 + bh;
    #pragma unroll
    for (int r = 0; r < 8; r++) {
        float2 a = unpack2(acc[r][0]), c = unpack2(acc[r][1]);
        *(float4*)(g_Hn + (zb*16 + vg*8 + r)*1024 + j0 + 4*pg) =
            make_float4(a.x, a.y, c.x, c.y);
    }
    if (vg == 0) {
        float2 sA = unpack2(sum0), sB = unpack2(sum1);
        *(float4*)(g_Hs + zb*1024 + j0 + 4*pg) = make_float4(sA.x, sA.y, sB.x, sB.y);
    }
}

// ---------------------------------------------------------------------------
// Kernel C: normalize + output projection. grid (8 b, 32 l-chunks of 32), 128 thr.
// Row-pair packed W (padded vs bank conflicts); x = (n0+n1)*rcp(s0+s1), dup'd.
// ---------------------------------------------------------------------------
__global__ __launch_bounds__(128) void outproj_kernel(
    const float* __restrict__ Wo, float* __restrict__ out)
{
    extern __shared__ char sm[];
    u64*   wp = (u64*)sm;                          // [64][129] row-pairs, padded
    u64*   xd = (u64*)(sm + 64*129*8);             // [32][32] dup'd normalized H
    float* rs = (float*)(sm + 64*129*8 + 32*32*8); // [8][32] 1/(s0+s1)

    int b = blockIdx.x;
    int l0 = blockIdx.y * 32;
    int tid = threadIdx.x;

    for (int e = tid; e < 8192; e += 128) {
        int rp = e >> 7, d = e & 127;
        wp[rp*129 + d] = pack2(Wo[(b*128 + 2*rp    )*128 + d],
                               Wo[(b*128 + 2*rp + 1)*128 + d]);
    }
    for (int e = tid; e < 256; e += 128) {
        int h = e >> 5, c = e & 31;
        float s = g_Hs[(b*8 + h)*1024 + l0 + c] + g_Hs[(64 + b*8 + h)*1024 + l0 + c];
        rs[e] = 1.0f / s;
    }

    int rowg = tid >> 3, colg = tid & 7;   // 16 x 8
    int rp0 = rowg*4, c0 = colg*4;

    u64 acc[4][4] = {};
    for (int ch = 0; ch < 4; ch++) {
        __syncthreads();
        for (int e = tid; e < 1024; e += 128) {
            int dd = e >> 5, c = e & 31;
            int d = ch*32 + dd, h = d >> 4, v = d & 15;
            int row = ((b*8 + h)*16 + v)*1024 + l0 + c;
            float n = g_Hn[row] + g_Hn[row + 1048576];
            xd[dd*32 + c] = dup2(n * rs[h*32 + c]);
        }
        __syncthreads();
        #pragma unroll 8
        for (int dd = 0; dd < 32; dd++) {
            u64 xr[4];
            #pragma unroll
            for (int c = 0; c < 4; c++) xr[c] = xd[dd*32 + c0 + c];
            #pragma unroll
            for (int p = 0; p < 4; p++) {
                u64 w = wp[(rp0 + p)*129 + ch*32 + dd];
                #pragma unroll
                for (int c = 0; c < 4; c++) fma2(acc[p][c], w, xr[c]);
            }
        }
    }
    #pragma unroll
    for (int p = 0; p < 4; p++) {
        float2 a0 = unpack2(acc[p][0]), a1 = unpack2(acc[p][1]);
        float2 a2 = unpack2(acc[p][2]), a3 = unpack2(acc[p][3]);
        int r = 2*(rp0 + p);
        *(float4*)(out + (b*128 + r    )*1024 + l0 + c0) = make_float4(a0.x, a1.x, a2.x, a3.x);
        *(float4*)(out + (b*128 + r + 1)*1024 + l0 + c0) = make_float4(a0.y, a1.y, a2.y, a3.y);
    }
}

// ---------------------------------------------------------------------------
extern "C" void kernel_launch(void* const* d_in, const int* in_sizes, int n_in,
                              void* d_out, int out_size)
{
    const float* x  = (const float*)d_in[0];
    const float* Wq = (const float*)d_in[1];
    const float* Wk = (const float*)d_in[2];
    const float* Wv = (const float*)d_in[3];
    const float* Wo = (const float*)d_in[4];
    float* out = (float*)d_out;

    const int smemA = 48*128*8 + 32*128*4;              // 65536
    const int smemB = 16384 + 32768 + 4096 + 4096;      // 57344
    const int smemC = 64*129*8 + 32*32*8 + 8*32*4;      // 75264
    cudaFuncSetAttribute(qkv_kernel,     cudaFuncAttributeMaxDynamicSharedMemorySize, smemA);
    cudaFuncSetAttribute(attn_kernel,    cudaFuncAttributeMaxDynamicSharedMemorySize, smemB);
    cudaFuncSetAttribute(outproj_kernel, cudaFuncAttributeMaxDynamicSharedMemorySize, smemC);

    qkv_kernel<<<dim3(64, 8), 128, smemA>>>(x, Wq, Wk, Wv);
    attn_kernel<<<dim3(64, 4, 2), 128, smemB>>>();
    outproj_kernel<<<dim3(8, 32), 128, smemC>>>(Wo, out);
}

// round 3
// speedup vs baseline: 1.3720x; 1.0869x over previous
#include <cuda_runtime.h>

#define BH 64
typedef unsigned long long u64;

// Scratch (device globals)
__device__ float g_Q[BH*16*1024];
__device__ float g_K[BH*16*1024];
__device__ float g_V[BH*16*1024];
__device__ float g_Hn[2*BH*16*1024];  // unnormalized numerators, [z][bh][v][l]
__device__ float g_Hs[2*BH*1024];     // colsums, [z][bh][l]

__device__ __forceinline__ void fma2(u64 &d, u64 a, u64 b) {
    asm("fma.rn.f32x2 %0, %1, %2, %0;" : "+l"(d) : "l"(a), "l"(b));
}
__device__ __forceinline__ void add2(u64 &d, u64 a) {
    asm("add.rn.f32x2 %0, %1, %0;" : "+l"(d) : "l"(a));
}
__device__ __forceinline__ u64 pack2(float lo, float hi) {
    u64 r; asm("mov.b64 %0, {%1, %2};" : "=l"(r) : "f"(lo), "f"(hi)); return r;
}
__device__ __forceinline__ float2 unpack2(u64 v) {
    float2 r; asm("mov.b64 {%0, %1}, %2;" : "=f"(r.x), "=f"(r.y) : "l"(v)); return r;
}
__device__ __forceinline__ u64 dup2(float v) { return pack2(v, v); }
__device__ __forceinline__ float ex2(float x) {
    float y; asm("ex2.approx.ftz.f32 %0, %1;" : "=f"(y) : "f"(x)); return y;
}

// ---------------------------------------------------------------------------
// Kernel A: QKV projection. grid (64 bh, 8 l-chunks of 128), 128 threads.
// Thread tile: 6 rows x 4 strided col-pairs (cp = colg + 16p), conflict-free.
// ---------------------------------------------------------------------------
__global__ __launch_bounds__(128) void qkv_kernel(
    const float* __restrict__ x,
    const float* __restrict__ Wq,
    const float* __restrict__ Wk,
    const float* __restrict__ Wv)
{
    extern __shared__ char sm[];
    float* ws = (float*)sm;                   // [48][128] 24KB
    float* xs = (float*)(sm + 48*128*4);      // [32][128] 16KB

    int bh = blockIdx.x, b = bh >> 3, h = bh & 7;
    int l0 = blockIdx.y * 128;
    int tid = threadIdx.x;

    for (int e = tid; e < 48*128; e += 128) {
        int r = e >> 7, d = e & 127;
        const float* W = (r < 16) ? Wq : ((r < 32) ? Wk : Wv);
        ws[e] = W[((h*8 + b)*16 + (r & 15))*128 + d];
    }

    int rowg = tid >> 4, colg = tid & 15;   // 8 x 16
    int r0 = rowg*6;

    u64 acc[6][4] = {};
    for (int ch = 0; ch < 4; ch++) {
        __syncthreads();
        for (int idx = tid; idx < 1024; idx += 128) {
            int dd = idx >> 5, c4 = (idx & 31) * 4;
            *(float4*)(xs + dd*128 + c4) =
                *(const float4*)(x + (b*128 + ch*32 + dd)*1024 + l0 + c4);
        }
        __syncthreads();
        #pragma unroll 8
        for (int dd = 0; dd < 32; dd++) {
            u64 xa[4];
            #pragma unroll
            for (int p = 0; p < 4; p++)
                xa[p] = *(const u64*)(xs + dd*128 + (colg + 16*p)*2);
            #pragma unroll
            for (int r = 0; r < 6; r++) {
                u64 w = dup2(ws[(r0 + r)*128 + ch*32 + dd]);
                #pragma unroll
                for (int p = 0; p < 4; p++) fma2(acc[r][p], w, xa[p]);
            }
        }
    }
    #pragma unroll
    for (int r = 0; r < 6; r++) {
        int gr = r0 + r;
        float* dst = (gr < 16) ? g_Q : ((gr < 32) ? g_K : g_V);
        float* base = dst + (bh*16 + (gr & 15))*1024 + l0;
        #pragma unroll
        for (int p = 0; p < 4; p++) {
            float2 a = unpack2(acc[r][p]);
            *(float2*)(base + (colg + 16*p)*2) = a;
        }
    }
}

// ---------------------------------------------------------------------------
// Kernel B: attention. grid (64 bh, 4 j-tiles of 256, 2 i-halves), 128 thr.
// Two-phase per 32-i block; P read back via single LDS.128.
// ---------------------------------------------------------------------------
__global__ __launch_bounds__(128) void attn_kernel()
{
    extern __shared__ char sm[];
    u64* Kp = (u64*)sm;                       // [16][128]  16KB
    u64* Ps = (u64*)(sm + 16384);             // [32][128]  32KB
    u64* Qd = (u64*)(sm + 16384 + 32768);     // [16][32]   4KB
    u64* Vd = Qd + 512;                       // [16][32]   4KB

    int bh = blockIdx.x;
    int j0 = blockIdx.y * 256;
    int z  = blockIdx.z;
    int tid = threadIdx.x;
    const float SCL = 0.25f * 1.4426950408889634f;  // scale * log2(e)

    for (int e = tid; e < 2048; e += 128) {
        int k = e >> 7, s = e & 127;
        float2 kv = *(const float2*)(g_K + (bh*16 + k)*1024 + j0 + 2*s);
        Kp[e] = pack2(kv.x * SCL, kv.y * SCL);
    }

    int i_base = z * 512;
    float qf[4], vf[4];
    #pragma unroll
    for (int w = 0; w < 4; w++) {
        int e = tid + w*128, k = e >> 5, ii = e & 31;
        qf[w] = g_Q[(bh*16 + k)*1024 + i_base + ii];
        vf[w] = g_V[(bh*16 + k)*1024 + i_base + ii];
    }

    int ig = tid >> 4, jg = tid & 15;
    int vg = tid >> 6, pg = tid & 63;

    u64 acc[8][2] = {};
    u64 sum0 = 0, sum1 = 0;

    for (int t = 0; t < 16; t++) {
        __syncthreads();
        #pragma unroll
        for (int w = 0; w < 4; w++) {
            int e = tid + w*128;
            Qd[e] = dup2(qf[w]);
            Vd[e] = dup2(vf[w]);
        }
        int tn = (t + 1 < 16) ? t + 1 : 15;
        #pragma unroll
        for (int w = 0; w < 4; w++) {
            int e = tid + w*128, k = e >> 5, ii = e & 31;
            qf[w] = g_Q[(bh*16 + k)*1024 + i_base + tn*32 + ii];
            vf[w] = g_V[(bh*16 + k)*1024 + i_base + tn*32 + ii];
        }
        __syncthreads();

        u64 s[4][8] = {};
        #pragma unroll
        for (int k = 0; k < 16; k++) {
            u64 qr[4];
            #pragma unroll
            for (int r = 0; r < 4; r++) qr[r] = Qd[k*32 + ig*4 + r];
            #pragma unroll
            for (int p = 0; p < 8; p++) {
                u64 kv = Kp[k*128 + p*16 + jg];
                #pragma unroll
                for (int r = 0; r < 4; r++) fma2(s[r][p], qr[r], kv);
            }
        }
        #pragma unroll
        for (int r = 0; r < 4; r++) {
            #pragma unroll
            for (int p = 0; p < 8; p++) {
                float2 sv = unpack2(s[r][p]);
                Ps[(ig*4 + r)*128 + p*16 + jg] = pack2(ex2(sv.x), ex2(sv.y));
            }
        }
        __syncthreads();

        #pragma unroll 4
        for (int ii = 0; ii < 32; ii++) {
            ulonglong2 P = *(const ulonglong2*)(Ps + ii*128 + 2*pg);
            add2(sum0, P.x); add2(sum1, P.y);
            #pragma unroll
            for (int r = 0; r < 8; r++) {
                u64 vv = Vd[(vg*8 + r)*32 + ii];
                fma2(acc[r][0], P.x, vv);
                fma2(acc[r][1], P.y, vv);
            }
        }
    }

    int zb = z*64 + bh;
    #pragma unroll
    for (int r = 0; r < 8; r++) {
        float2 a = unpack2(acc[r][0]), c = unpack2(acc[r][1]);
        *(float4*)(g_Hn + (zb*16 + vg*8 + r)*1024 + j0 + 4*pg) =
            make_float4(a.x, a.y, c.x, c.y);
    }
    if (vg == 0) {
        float2 sA = unpack2(sum0), sB = unpack2(sum1);
        *(float4*)(g_Hs + zb*1024 + j0 + 4*pg) = make_float4(sA.x, sA.y, sB.x, sB.y);
    }
}

// ---------------------------------------------------------------------------
// Kernel C: normalize + output projection. grid (8 b, 32 l-chunks of 32), 128 thr.
// Row-pair packed W x dup'd-column x (valid 2-row x 1-col product per FMA2).
// Thread tile: 4 row-pairs x 4 strided dup-columns (c = colg + 8p).
// ---------------------------------------------------------------------------
__global__ __launch_bounds__(128) void outproj_kernel(
    const float* __restrict__ Wo, float* __restrict__ out)
{
    extern __shared__ char sm[];
    u64*   wp = (u64*)sm;                          // [64][128] row-pairs 64KB
    u64*   xd = (u64*)(sm + 64*128*8);             // [32][32] dup'd norm. H 8KB
    float* rs = (float*)(sm + 64*128*8 + 32*32*8); // [8][32]  1KB

    int b = blockIdx.x;
    int l0 = blockIdx.y * 32;
    int tid = threadIdx.x;

    for (int e = tid; e < 8192; e += 128) {
        int rp = e >> 7, d = e & 127;
        wp[e] = pack2(Wo[(b*128 + 2*rp    )*128 + d],
                      Wo[(b*128 + 2*rp + 1)*128 + d]);
    }
    for (int e = tid; e < 256; e += 128) {
        int h = e >> 5, c = e & 31;
        float s = g_Hs[(b*8 + h)*1024 + l0 + c] + g_Hs[(64 + b*8 + h)*1024 + l0 + c];
        rs[e] = 1.0f / s;
    }

    int rowg = tid >> 3, colg = tid & 7;   // 16 x 8
    int rp0 = rowg*4;

    u64 acc[4][4] = {};
    for (int ch = 0; ch < 4; ch++) {
        __syncthreads();
        for (int e = tid; e < 1024; e += 128) {
            int dd = e >> 5, c = e & 31;
            int d = ch*32 + dd, h = d >> 4, v = d & 15;
            int row = ((b*8 + h)*16 + v)*1024 + l0 + c;
            float n = g_Hn[row] + g_Hn[row + 1048576];
            xd[dd*32 + c] = dup2(n * rs[h*32 + c]);
        }
        __syncthreads();
        #pragma unroll 8
        for (int dd = 0; dd < 32; dd++) {
            u64 xr[4];
            #pragma unroll
            for (int p = 0; p < 4; p++) xr[p] = xd[dd*32 + colg + 8*p];  // consecutive per p
            #pragma unroll
            for (int r = 0; r < 4; r++) {
                u64 w = wp[(rp0 + r)*128 + ch*32 + dd];
                #pragma unroll
                for (int p = 0; p < 4; p++) fma2(acc[r][p], w, xr[p]);
            }
        }
    }
    #pragma unroll
    for (int r = 0; r < 4; r++) {
        int row = 2*(rp0 + r);
        #pragma unroll
        for (int p = 0; p < 4; p++) {
            float2 a = unpack2(acc[r][p]);   // (row, row+1) at column c
            int c = colg + 8*p;
            out[(b*128 + row    )*1024 + l0 + c] = a.x;
            out[(b*128 + row + 1)*1024 + l0 + c] = a.y;
        }
    }
}

// ---------------------------------------------------------------------------
extern "C" void kernel_launch(void* const* d_in, const int* in_sizes, int n_in,
                              void* d_out, int out_size)
{
    const float* x  = (const float*)d_in[0];
    const float* Wq = (const float*)d_in[1];
    const float* Wk = (const float*)d_in[2];
    const float* Wv = (const float*)d_in[3];
    const float* Wo = (const float*)d_in[4];
    float* out = (float*)d_out;

    const int smemA = 48*128*4 + 32*128*4;              // 40960
    const int smemB = 16384 + 32768 + 4096 + 4096;      // 57344
    const int smemC = 64*128*8 + 32*32*8 + 8*32*4;      // 74752
    cudaFuncSetAttribute(qkv_kernel,     cudaFuncAttributeMaxDynamicSharedMemorySize, smemA);
    cudaFuncSetAttribute(attn_kernel,    cudaFuncAttributeMaxDynamicSharedMemorySize, smemB);
    cudaFuncSetAttribute(outproj_kernel, cudaFuncAttributeMaxDynamicSharedMemorySize, smemC);

    qkv_kernel<<<dim3(64, 8), 128, smemA>>>(x, Wq, Wk, Wv);
    attn_kernel<<<dim3(64, 4, 2), 128, smemB>>>();
    outproj_kernel<<<dim3(8, 32), 128, smemC>>>(Wo, out);
}